// round 13
// baseline (speedup 1.0000x reference)
#include <cuda_runtime.h>
#include <cuda_bf16.h>
#include <math.h>

// Problem dims (fixed by the dataset)
#define BB 16
#define TT 4096
#define HH 256
#define PP 64

#define NSPLIT 8   // split-K factor for the pf GEMM
#define NF 768     // fused k1|v1|q2 width

// ---------------- scratch (no allocation allowed) ----------------
__device__ float g_kvq[BB * TT * NF];  // fused [k1 | v1 | q2], 192 MB
__device__ float g_q1[PP * HH];
__device__ float g_pf[BB * PP * HH];
__device__ float g_pfp[NSPLIT * BB * PP * HH];  // split-K partials (8 MB)
__device__ float g_k2[BB * PP * HH];
__device__ float g_v2[BB * PP * HH];
__device__ float g_s1[BB * PP * TT];   // 16 MB; reused as s2 (stream-ordered)
__device__ float g_wf[NF * HH];        // fused rounded weights [K1w;V1w;Qw]
__device__ float g_wr2[3 * HH * HH];   // rounded Q1w, Kw, Vw
__device__ float g_b3[NF];             // fused biases [K1b;V1b;Qb]

// ---------------- helpers ------------------------------------------------
__device__ __forceinline__ void mma_tf32(float* c, const unsigned* a, const unsigned* b) {
    asm("mma.sync.aligned.m16n8k8.row.col.f32.tf32.tf32.f32 "
        "{%0,%1,%2,%3},{%4,%5,%6,%7},{%8,%9},{%0,%1,%2,%3};"
        : "+f"(c[0]), "+f"(c[1]), "+f"(c[2]), "+f"(c[3])
        : "r"(a[0]), "r"(a[1]), "r"(a[2]), "r"(a[3]), "r"(b[0]), "r"(b[1]));
}

// RNA round to the tf32 grid. MMA truncation of such a value is the identity.
__device__ __forceinline__ unsigned rnd13(unsigned u) { return u + 0x1000u; }
__device__ __forceinline__ float roundtf(float f) {
    unsigned u = __float_as_uint(f);
    u = (u + 0x1000u) & 0xFFFFE000u;
    return __uint_as_float(u);
}

__device__ __forceinline__ void ldsm_x4(unsigned& r0, unsigned& r1,
                                        unsigned& r2, unsigned& r3, unsigned addr) {
    asm volatile("ldmatrix.sync.aligned.m8n8.x4.shared.b16 {%0,%1,%2,%3}, [%4];"
                 : "=r"(r0), "=r"(r1), "=r"(r2), "=r"(r3) : "r"(addr));
}

__device__ __forceinline__ void cpa16s(unsigned dst, const void* src) {
    asm volatile("cp.async.cg.shared.global [%0], [%1], 16;" :: "r"(dst), "l"(src));
}
__device__ __forceinline__ void cp_commit() {
    asm volatile("cp.async.commit_group;");
}
template<int N>
__device__ __forceinline__ void cp_wait() {
    asm volatile("cp.async.wait_group %0;" :: "n"(N));
}

// ---------------- TF32 tensor-core GEMM, 3-stage cp.async + ldmatrix -----
#define BK 32
#define NSTG 3

template<int BM, int BN, bool BTRANS>
struct SmemSizes {
    static constexpr int AWORDS = BM * BK;
    static constexpr int BSTNN  = BN + 8;
    static constexpr int BWORDS = BTRANS ? BN * BK : BK * BSTNN;
    static constexpr int STW    = AWORDS + BWORDS;     // words per stage
    static constexpr int BYTES  = NSTG * STW * 4;
};

template<int BM, int BN, int WM, int WN, bool BTRANS, bool RNDA, bool RNDOUT>
__global__ __launch_bounds__(256, 2) void gemm_tc(
    const float* __restrict__ A, long long sA, int lda,
    const float* __restrict__ B, long long sB, int ldb,
    float* __restrict__ C, long long sC, int ldc,
    int Kloop,
    const float* __restrict__ bias, float scale,
    const float* __restrict__ lens,
    const float* __restrict__ klim,
    int nsplit, long long sSplit)
{
    constexpr int WCOLS = BN / WN;
    constexpr int MT  = WM / 16;
    constexpr int NTt = WN / 8;
    constexpr int NJ  = NTt / 2;
    constexpr int AWORDS = SmemSizes<BM, BN, BTRANS>::AWORDS;
    constexpr int BSTNN  = SmemSizes<BM, BN, BTRANS>::BSTNN;
    constexpr int STW    = SmemSizes<BM, BN, BTRANS>::STW;

    extern __shared__ unsigned smem_dyn[];
    const unsigned sbase = (unsigned)__cvta_generic_to_shared(smem_dyn);

    const int bz = blockIdx.z;
    const int b  = bz / nsplit;
    const int ks = bz % nsplit;

    const float* Ab = A + (long long)b * sA + (long long)ks * Kloop;
    const float* Bb;
    if (BTRANS) Bb = B + (long long)b * sB + (long long)ks * Kloop;
    else        Bb = B + (long long)b * sB + (long long)ks * Kloop * ldb;
    float* Cb = C + (long long)b * sC + (long long)ks * sSplit;

    const int m0 = blockIdx.y * BM;
    const int n0 = blockIdx.x * BN;

    float maskLen = 3.0e38f;
    if (lens) {
        float L = lens[b];
        scale = rsqrtf(L);
        maskLen = L;
        if ((float)n0 >= maskLen) return;   // fully masked; softmax zero-fills
    }

    int nIter = Kloop / BK;
    if (klim) {
        int eff = (int)klim[b] - ks * Kloop;
        eff = eff < 0 ? 0 : (eff > Kloop ? Kloop : eff);
        nIter = (eff + BK - 1) / BK;
    }

    const int tid  = threadIdx.x;
    const int lane = tid & 31;
    const int wid  = tid >> 5;
    const int wm   = wid / WCOLS;
    const int wn   = wid % WCOLS;
    const int g    = lane >> 2;
    const int t4   = lane & 3;
    const int l7   = lane & 7;
    const int lr15 = lane & 15;
    const int hb   = lane >> 4;
    const int qb   = (lane >> 3) & 1;

    const int ar = tid >> 3;
    const int aq = tid & 7;

    auto loadA = [&](int s, int k0) {
        const unsigned abase = sbase + (s * STW) * 4;
#pragma unroll
        for (int i = 0; i < BM / 32; i++) {
            const int row = ar + 32 * i;
            cpa16s(abase + (row * BK + ((aq ^ (row & 7)) << 2)) * 4,
                   Ab + (long long)(m0 + row) * lda + k0 + (aq << 2));
        }
    };
    auto loadB = [&](int s, int k0) {
        const unsigned bbase = sbase + (s * STW + AWORDS) * 4;
        if (BTRANS) {
#pragma unroll
            for (int i = 0; i < BN / 32; i++) {
                const int row = ar + 32 * i;
                cpa16s(bbase + (row * BK + ((aq ^ (row & 7)) << 2)) * 4,
                       Bb + (long long)(n0 + row) * ldb + k0 + (aq << 2));
            }
        } else {
            constexpr int QPR = BN / 4;
            constexpr int RPP = 256 / QPR;
            const int bk = tid / QPR;
            const int bq = tid % QPR;
#pragma unroll
            for (int i = 0; i < BK / RPP; i++) {
                const int krow = bk + RPP * i;
                cpa16s(bbase + (krow * BSTNN + bq * 4) * 4,
                       Bb + (long long)(k0 + krow) * ldb + n0 + bq * 4);
            }
        }
    };

    unsigned aRowOff[MT];
#pragma unroll
    for (int i = 0; i < MT; i++)
        aRowOff[i] = (wm * WM + i * 16 + lr15) * BK * 4;
    unsigned bRowOff[NJ];
    if (BTRANS) {
#pragma unroll
        for (int jj = 0; jj < NJ; jj++)
            bRowOff[jj] = (wn * WN + jj * 16 + hb * 8 + l7) * BK * 4;
    }

    float acc[MT][NTt][4];
#pragma unroll
    for (int i = 0; i < MT; i++)
#pragma unroll
        for (int j = 0; j < NTt; j++)
#pragma unroll
            for (int q = 0; q < 4; q++) acc[i][j][q] = 0.f;

    if (nIter > 0) {
        loadA(0, 0);
        loadB(0, 0);
        cp_commit();
        if (nIter > 1) { loadA(1, BK); loadB(1, BK); }
        cp_commit();

        int cb = 0;
        for (int it = 0; it < nIter; it++) {
            if (it + 2 < nIter) {
                const int nbuf = (cb == 0) ? 2 : cb - 1;
                loadA(nbuf, (it + 2) * BK);
                loadB(nbuf, (it + 2) * BK);
            }
            cp_commit();
            cp_wait<2>();
            __syncthreads();

            const unsigned aSt = sbase + (cb * STW) * 4;
            const unsigned bSt = aSt + AWORDS * 4;
            const unsigned* BsNN = smem_dyn + cb * STW + AWORDS;

#pragma unroll
            for (int kss = 0; kss < BK / 8; kss++) {
                const int q0 = kss * 2;
                unsigned af[MT][4];
#pragma unroll
                for (int i = 0; i < MT; i++) {
                    ldsm_x4(af[i][0], af[i][1], af[i][2], af[i][3],
                            aSt + aRowOff[i] + (unsigned)((((q0 + hb) ^ l7)) << 4));
                    if (RNDA) {
                        af[i][0] = rnd13(af[i][0]); af[i][1] = rnd13(af[i][1]);
                        af[i][2] = rnd13(af[i][2]); af[i][3] = rnd13(af[i][3]);
                    }
                }
                unsigned bf[NTt][2];
                if (BTRANS) {
#pragma unroll
                    for (int jj = 0; jj < NJ; jj++) {
                        unsigned w0, w1, w2, w3;
                        ldsm_x4(w0, w1, w2, w3,
                                bSt + bRowOff[jj] + (unsigned)((((q0 + qb) ^ l7)) << 4));
                        bf[2 * jj][0]     = w0;
                        bf[2 * jj][1]     = w1;
                        bf[2 * jj + 1][0] = w2;
                        bf[2 * jj + 1][1] = w3;
                    }
                } else {
                    const int kb = kss * 8;
#pragma unroll
                    for (int j = 0; j < NTt; j++) {
                        const int n = wn * WN + j * 8 + g;
                        bf[j][0] = BsNN[(kb + t4)     * BSTNN + n];
                        bf[j][1] = BsNN[(kb + t4 + 4) * BSTNN + n];
                    }
                }
#pragma unroll
                for (int i = 0; i < MT; i++)
#pragma unroll
                    for (int j = 0; j < NTt; j++)
                        mma_tf32(acc[i][j], af[i], bf[j]);
            }
            __syncthreads();
            cb = (cb == 2) ? 0 : cb + 1;
        }
    }

    // ---- epilogue ----
#pragma unroll
    for (int i = 0; i < MT; i++) {
        const int mrow = m0 + wm * WM + i * 16 + g;
#pragma unroll
        for (int j = 0; j < NTt; j++) {
            const int ncol = n0 + wn * WN + j * 8 + 2 * t4;
            float b0 = bias ? bias[ncol]     : 0.f;
            float b1 = bias ? bias[ncol + 1] : 0.f;
            float v0 = acc[i][j][0] * scale + b0;
            float v1 = acc[i][j][1] * scale + b1;
            float v2 = acc[i][j][2] * scale + b0;
            float v3 = acc[i][j][3] * scale + b1;
            if (lens) {
                if ((float)ncol     >= maskLen) { v0 = -1e9f; v2 = -1e9f; }
                if ((float)(ncol+1) >= maskLen) { v1 = -1e9f; v3 = -1e9f; }
            }
            if (RNDOUT) {
                v0 = roundtf(v0); v1 = roundtf(v1);
                v2 = roundtf(v2); v3 = roundtf(v3);
            }
            *(float2*)(Cb + (long long)mrow * ldc + ncol)       = make_float2(v0, v1);
            *(float2*)(Cb + (long long)(mrow + 8) * ldc + ncol) = make_float2(v2, v3);
        }
    }
}

// ---------------- fused softmax2 + out-GEMM -------------------------------
// A = raw scores2 tile [128 x 64] (K = P = 64, fully resident); softmax each
// row in smem (warp-per-row, same lane/shfl order as the old softmax_rows),
// round to tf32, then D = softmax(A) @ v2 over 8 k8 substeps.
#define O_AW (128 * 64)        // A tile words
#define O_BST 72               // B row stride words (64 + 8)
#define O_SMEM ((O_AW + 64 * O_BST) * 4)

__global__ __launch_bounds__(256, 2) void attn2_out(
    const float* __restrict__ S,   // [B, T, P] raw scores2
    const float* __restrict__ V,   // [B, P, H] v2 (pre-rounded)
    float* __restrict__ O)         // [B, T, H]
{
    extern __shared__ unsigned smem_dyn[];
    const unsigned sbase = (unsigned)__cvta_generic_to_shared(smem_dyn);
    unsigned* As = smem_dyn;
    const unsigned* Bs = smem_dyn + O_AW;

    const int b  = blockIdx.z;
    const int m0 = blockIdx.y * 128;
    const int n0 = blockIdx.x * 64;

    const float* Sb = S + (long long)b * TT * PP + (long long)m0 * PP;
    const float* Vb = V + (long long)b * PP * HH;
    float* Ob = O + (long long)b * TT * HH;

    const int tid  = threadIdx.x;
    const int lane = tid & 31;
    const int wid  = tid >> 5;

    // ---- load A: 128 rows x 16 quads, swizzled ----
#pragma unroll
    for (int i = 0; i < 8; i++) {
        const int idx = tid + i * 256;
        const int r = idx >> 4;
        const int q = idx & 15;
        cpa16s(sbase + (r * 64 + ((q ^ (r & 7)) << 2)) * 4, Sb + r * 64 + q * 4);
    }
    // ---- load B: v2 [64 k-rows x 64 cols] -> [k][n] padded ----
#pragma unroll
    for (int i = 0; i < 4; i++) {
        const int idx = tid + i * 256;
        const int k  = idx >> 4;
        const int qn = idx & 15;
        cpa16s(sbase + (O_AW + k * O_BST + qn * 4) * 4, Vb + k * HH + n0 + qn * 4);
    }
    cp_commit();
    cp_wait<0>();
    __syncthreads();

    // ---- softmax rows of A (warp per row, 16 rows per warp) ----
#pragma unroll
    for (int i = 0; i < 16; i++) {
        const int r = wid * 16 + i;
        const int c0 = lane, c1 = lane + 32;
        const int w0 = r * 64 + (((c0 >> 2) ^ (r & 7)) << 2) + (c0 & 3);
        const int w1 = r * 64 + (((c1 >> 2) ^ (r & 7)) << 2) + (c1 & 3);
        const float v0 = __uint_as_float(As[w0]);
        const float v1 = __uint_as_float(As[w1]);
        float m = fmaxf(fmaxf(-3.0e38f, v0), v1);
#pragma unroll
        for (int o = 16; o; o >>= 1) m = fmaxf(m, __shfl_xor_sync(0xffffffffu, m, o));
        const float e0 = __expf(v0 - m);
        const float e1 = __expf(v1 - m);
        float s = e0 + e1;
#pragma unroll
        for (int o = 16; o; o >>= 1) s += __shfl_xor_sync(0xffffffffu, s, o);
        const float inv = 1.f / s;
        As[w0] = __float_as_uint(roundtf(e0 * inv));
        As[w1] = __float_as_uint(roundtf(e1 * inv));
    }
    __syncthreads();

    // ---- MMA: 128x64 tile, 8 warps (2x4), warp tile 64x16 ----
    const int wm = wid >> 2;        // 0..1
    const int wn = wid & 3;         // 0..3
    const int g    = lane >> 2;
    const int t4   = lane & 3;
    const int l7   = lane & 7;
    const int lr15 = lane & 15;
    const int hb   = lane >> 4;

    unsigned aRow[4];
#pragma unroll
    for (int i = 0; i < 4; i++)
        aRow[i] = (wm * 64 + i * 16 + lr15) * 64 * 4;

    float acc[4][2][4];
#pragma unroll
    for (int i = 0; i < 4; i++)
#pragma unroll
        for (int j = 0; j < 2; j++)
#pragma unroll
            for (int q = 0; q < 4; q++) acc[i][j][q] = 0.f;

#pragma unroll
    for (int kss = 0; kss < 8; kss++) {
        const int q0 = kss * 2;
        const int kb = kss * 8;
        unsigned af[4][4];
#pragma unroll
        for (int i = 0; i < 4; i++)
            ldsm_x4(af[i][0], af[i][1], af[i][2], af[i][3],
                    sbase + aRow[i] + (unsigned)((((q0 + hb) ^ l7)) << 4));
        unsigned bf[2][2];
#pragma unroll
        for (int j = 0; j < 2; j++) {
            const int n = wn * 16 + j * 8 + g;
            bf[j][0] = Bs[(kb + t4)     * O_BST + n];
            bf[j][1] = Bs[(kb + t4 + 4) * O_BST + n];
        }
#pragma unroll
        for (int i = 0; i < 4; i++)
#pragma unroll
            for (int j = 0; j < 2; j++)
                mma_tf32(acc[i][j], af[i], bf[j]);
    }

    // ---- epilogue ----
#pragma unroll
    for (int i = 0; i < 4; i++) {
        const int mrow = m0 + wm * 64 + i * 16 + g;
#pragma unroll
        for (int j = 0; j < 2; j++) {
            const int ncol = n0 + wn * 16 + j * 8 + 2 * t4;
            *(float2*)(Ob + (long long)mrow * HH + ncol) =
                make_float2(acc[i][j][0], acc[i][j][1]);
            *(float2*)(Ob + (long long)(mrow + 8) * HH + ncol) =
                make_float2(acc[i][j][2], acc[i][j][3]);
        }
    }
}

// ---------------- weight prep ---------------------------------------------
__global__ void prep_weights(const float* K1w, const float* V1w, const float* Qw,
                             const float* Q1w, const float* Kw, const float* Vw,
                             float* wf, float* wr2)
{
    const int seg = blockIdx.y;
    const float* src;
    switch (seg) {
        case 0: src = K1w; break; case 1: src = V1w; break;
        case 2: src = Qw;  break; case 3: src = Q1w; break;
        case 4: src = Kw;  break; default: src = Vw; break;
    }
    const int i = blockIdx.x * blockDim.x + threadIdx.x;
    const float v = roundtf(src[i]);
    if (seg < 3) wf[seg * HH * HH + i] = v;
    else         wr2[(seg - 3) * HH * HH + i] = v;
}

__global__ void fuse_bias(const float* K1b, const float* V1b, const float* Qb,
                          float* b3)
{
    const int j = blockIdx.x * blockDim.x + threadIdx.x;
    b3[j] = (j < 256) ? K1b[j] : (j < 512) ? V1b[j - 256] : Qb[j - 512];
}

// ---------------- split-K reduce ------------------------------------------
__global__ void reduce_splits(const float* __restrict__ part,
                              float* __restrict__ out,
                              int n, long long stride)
{
    const int i = blockIdx.x * blockDim.x + threadIdx.x;
    if (i >= n) return;
    float s = 0.f;
#pragma unroll
    for (int k = 0; k < NSPLIT; k++) s += part[(long long)k * stride + i];
    out[i] = roundtf(s);
}

// ---------------- softmax, one 256-thread block per row -------------------
__global__ void softmax_row_block(float* __restrict__ x, int cols,
                                  const float* __restrict__ lens, int rpb)
{
    const int row = blockIdx.x;
    const int tid = threadIdx.x;
    const int lane = tid & 31;
    const int wid = tid >> 5;
    float* p = x + (long long)row * cols;

    const int L = lens ? (int)lens[row / rpb] : cols;

    __shared__ float red[8];

    float m = -3.0e38f;
    for (int c = tid; c < L; c += 256) m = fmaxf(m, p[c]);
#pragma unroll
    for (int o = 16; o; o >>= 1) m = fmaxf(m, __shfl_xor_sync(0xffffffffu, m, o));
    if (lane == 0) red[wid] = m;
    __syncthreads();
    if (wid == 0) {
        float t = red[lane & 7];
#pragma unroll
        for (int o = 4; o; o >>= 1) t = fmaxf(t, __shfl_xor_sync(0xffffffffu, t, o));
        if (lane == 0) red[0] = t;
    }
    __syncthreads();
    m = red[0];
    __syncthreads();

    float s = 0.f;
    for (int c = tid; c < L; c += 256) {
        const float e = __expf(p[c] - m);
        p[c] = e;
        s += e;
    }
#pragma unroll
    for (int o = 16; o; o >>= 1) s += __shfl_xor_sync(0xffffffffu, s, o);
    if (lane == 0) red[wid] = s;
    __syncthreads();
    if (wid == 0) {
        float t = red[lane & 7];
#pragma unroll
        for (int o = 4; o; o >>= 1) t += __shfl_xor_sync(0xffffffffu, t, o);
        if (lane == 0) red[0] = t;
    }
    __syncthreads();
    const float inv = 1.f / red[0];

    for (int c = tid; c < L; c += 256) p[c] = roundtf(p[c] * inv);
    for (int c = L + tid; c < cols; c += 256) p[c] = 0.f;
}

// ---------------- launch helper -------------------------------------------
template<int BM, int BN, int WM, int WN, bool BTRANS, bool RNDA, bool RNDOUT>
static void launch_gemm(dim3 grid,
                        const float* A, long long sA, int lda,
                        const float* B, long long sB, int ldb,
                        float* C, long long sC, int ldc,
                        int Kloop,
                        const float* bias, float scale,
                        const float* lens, const float* klim,
                        int nsplit, long long sSplit)
{
    constexpr int SMEM = SmemSizes<BM, BN, BTRANS>::BYTES;
    cudaFuncSetAttribute(gemm_tc<BM, BN, WM, WN, BTRANS, RNDA, RNDOUT>,
                         cudaFuncAttributeMaxDynamicSharedMemorySize, SMEM);
    gemm_tc<BM, BN, WM, WN, BTRANS, RNDA, RNDOUT><<<grid, 256, SMEM>>>(
        A, sA, lda, B, sB, ldb, C, sC, ldc, Kloop, bias, scale, lens, klim,
        nsplit, sSplit);
}

// ---------------- launch ---------------------------------------------------
extern "C" void kernel_launch(void* const* d_in, const int* in_sizes, int n_in,
                              void* d_out, int out_size)
{
    const float* hs    = (const float*)d_in[0];
    const float* proto = (const float*)d_in[1];
    const float* lens  = (const float*)d_in[2];
    // d_in[3] = mask (bool) — unused; reconstructed from lens
    const float* Q1w = (const float*)d_in[4];
    const float* Q1b = (const float*)d_in[5];
    const float* K1w = (const float*)d_in[6];
    const float* K1b = (const float*)d_in[7];
    const float* V1w = (const float*)d_in[8];
    const float* V1b = (const float*)d_in[9];
    const float* Qw  = (const float*)d_in[10];
    const float* Qb  = (const float*)d_in[11];
    const float* Kw  = (const float*)d_in[12];
    const float* Kb  = (const float*)d_in[13];
    const float* Vw  = (const float*)d_in[14];
    const float* Vb  = (const float*)d_in[15];
    float* out = (float*)d_out;

    float *kvq, *q1, *pf, *pfp, *k2, *v2, *s1, *wf, *wr2, *b3;
    cudaGetSymbolAddress((void**)&kvq, g_kvq);
    cudaGetSymbolAddress((void**)&q1, g_q1);
    cudaGetSymbolAddress((void**)&pf, g_pf);
    cudaGetSymbolAddress((void**)&pfp, g_pfp);
    cudaGetSymbolAddress((void**)&k2, g_k2);
    cudaGetSymbolAddress((void**)&v2, g_v2);
    cudaGetSymbolAddress((void**)&s1, g_s1);
    cudaGetSymbolAddress((void**)&wf, g_wf);
    cudaGetSymbolAddress((void**)&wr2, g_wr2);
    cudaGetSymbolAddress((void**)&b3, g_b3);
    float* s2 = s1;   // safe reuse: s1 fully consumed before scores2 written

    const int BT = BB * TT;        // 65536
    const int BP = BB * PP;        // 1024
    const long long TH = (long long)TT * HH;
    const long long PH = (long long)PP * HH;
    const long long PT = (long long)PP * TT;
    const long long TP = (long long)TT * PP;
    const long long TF = (long long)TT * NF;

    // weight prep
    prep_weights<<<dim3(HH * HH / 256, 6), 256>>>(K1w, V1w, Qw, Q1w, Kw, Vw, wf, wr2);
    fuse_bias<<<3, 256>>>(K1b, V1b, Qb, b3);
    const float* rQ1w = wr2 + 0 * HH * HH;
    const float* rKw  = wr2 + 1 * HH * HH;
    const float* rVw  = wr2 + 2 * HH * HH;

    // q1 = proto @ Q1_w^T + Q1_b                    [64, 256]
    launch_gemm<64, 128, 32, 32, true, true, true>(dim3(HH / 128, 1, 1),
        proto, 0, HH, rQ1w, 0, HH, q1, 0, HH, HH, Q1b, 1.f, nullptr, nullptr, 1, 0);

    // fused k1|v1|q2 over all tokens                [65536, 768]
    launch_gemm<128, 128, 64, 32, true, true, true>(dim3(NF / 128, BT / 128, 1),
        hs, 0, HH, wf, 0, HH, kvq, 0, NF, HH, b3, 1.f, nullptr, nullptr, 1, 0);

    // scores1[b,p,t] = q1 . k1 * rsqrt(len_b); masked tiles skipped
    launch_gemm<64, 128, 32, 32, true, false, false>(dim3(TT / 128, 1, BB),
        q1, 0, HH, kvq + 0, TF, NF, s1, PT, TT, HH, nullptr, 1.f, lens, nullptr, 1, 0);

    softmax_row_block<<<BP, 256>>>(s1, TT, lens, PP);

    // pf[b] = attn1 @ v1   (split-K x8, per-batch K limit) [64, 256]/batch
    launch_gemm<64, 64, 32, 16, false, false, false>(dim3(HH / 64, 1, BB * NSPLIT),
        s1, PT, TT, kvq + 256, TF, NF, pfp, PH, HH, TT / NSPLIT,
        nullptr, 1.f, nullptr, lens, NSPLIT, (long long)BB * PP * HH);
    reduce_splits<<<(BB * PP * HH + 255) / 256, 256>>>(
        pfp, pf, BB * PP * HH, (long long)BB * PP * HH);

    // k2 / v2 = pf @ {K,V}_w^T + b                  [1024, 256]
    launch_gemm<64, 128, 32, 32, true, false, true>(dim3(HH / 128, BP / 64, 1),
        pf, 0, HH, rKw, 0, HH, k2, 0, HH, HH, Kb, 1.f, nullptr, nullptr, 1, 0);
    launch_gemm<64, 128, 32, 32, true, false, true>(dim3(HH / 128, BP / 64, 1),
        pf, 0, HH, rVw, 0, HH, v2, 0, HH, HH, Vb, 1.f, nullptr, nullptr, 1, 0);

    // scores2[b,t,p] = q2 . k2 / sqrt(P)  (raw; softmax fused into attn2_out)
    launch_gemm<128, 64, 32, 32, true, false, false>(dim3(PP / 64, TT / 128, BB),
        kvq + 512, TF, NF, k2, PH, HH, s2, TP, PP, HH,
        nullptr, 0.125f, nullptr, nullptr, 1, 0);

    // out[b] = softmax(scores2) @ v2   — fused     [4096, 256] per batch
    cudaFuncSetAttribute(attn2_out,
                         cudaFuncAttributeMaxDynamicSharedMemorySize, O_SMEM);
    attn2_out<<<dim3(HH / 64, TT / 128, BB), 256, O_SMEM>>>(s2, v2, out);
}

// round 14
// speedup vs baseline: 1.0659x; 1.0659x over previous
#include <cuda_runtime.h>
#include <cuda_bf16.h>
#include <math.h>

// Problem dims (fixed by the dataset)
#define BB 16
#define TT 4096
#define HH 256
#define PP 64

#define NSPLIT 8   // split-K factor for the pf GEMM
#define NF 768     // fused k1|v1|q2 width

// ---------------- scratch (no allocation allowed) ----------------
__device__ float g_kvq[BB * TT * NF];  // fused [k1 | v1 | q2], 192 MB
__device__ float g_q1[PP * HH];
__device__ float g_pf[BB * PP * HH];
__device__ float g_pfp[NSPLIT * BB * PP * HH];  // split-K partials (8 MB)
__device__ float g_k2[BB * PP * HH];
__device__ float g_v2[BB * PP * HH];
__device__ float g_s1[BB * PP * TT];   // 16 MB; reused as s2 (stream-ordered)
__device__ float g_wf[NF * HH];        // fused rounded weights [K1w;V1w;Qw]
__device__ float g_wr2[3 * HH * HH];   // rounded Q1w, Kw, Vw
__device__ float g_b3[NF];             // fused biases [K1b;V1b;Qb]

// ---------------- helpers ------------------------------------------------
__device__ __forceinline__ void mma_tf32(float* c, const unsigned* a, const unsigned* b) {
    asm("mma.sync.aligned.m16n8k8.row.col.f32.tf32.tf32.f32 "
        "{%0,%1,%2,%3},{%4,%5,%6,%7},{%8,%9},{%0,%1,%2,%3};"
        : "+f"(c[0]), "+f"(c[1]), "+f"(c[2]), "+f"(c[3])
        : "r"(a[0]), "r"(a[1]), "r"(a[2]), "r"(a[3]), "r"(b[0]), "r"(b[1]));
}

// RNA round to the tf32 grid. MMA truncation of such a value is the identity.
__device__ __forceinline__ unsigned rnd13(unsigned u) { return u + 0x1000u; }
__device__ __forceinline__ float roundtf(float f) {
    unsigned u = __float_as_uint(f);
    u = (u + 0x1000u) & 0xFFFFE000u;
    return __uint_as_float(u);
}

__device__ __forceinline__ void ldsm_x4(unsigned& r0, unsigned& r1,
                                        unsigned& r2, unsigned& r3, unsigned addr) {
    asm volatile("ldmatrix.sync.aligned.m8n8.x4.shared.b16 {%0,%1,%2,%3}, [%4];"
                 : "=r"(r0), "=r"(r1), "=r"(r2), "=r"(r3) : "r"(addr));
}

__device__ __forceinline__ void cpa16s(unsigned dst, const void* src) {
    asm volatile("cp.async.cg.shared.global [%0], [%1], 16;" :: "r"(dst), "l"(src));
}
__device__ __forceinline__ void cp_commit() {
    asm volatile("cp.async.commit_group;");
}
template<int N>
__device__ __forceinline__ void cp_wait() {
    asm volatile("cp.async.wait_group %0;" :: "n"(N));
}

// ---------------- TF32 tensor-core GEMM, 3-stage cp.async + ldmatrix -----
// C[m,n] = sum_k A[m,k] * B'[k,n]
//   BTRANS: B' = B^T, B [N,K] row-major; else B' = B, [K,N] row-major.
// RNDA: rnd13 on A fragments (raw-fp32 A inputs).
// RNDOUT: round epilogue output to tf32 grid.
// SMAX: fuse row softmax into epilogue (requires BM=128, BN=64=N, WM=WN=32;
//       softmax order identical to softmax_rows -> bit-identical output).
// lens: per-batch mask+scale (s1); fully-masked tiles exit early.
// klim: per-batch K limit (pf) — trailing K blocks are exact zeros, skipped.
#define BK 32
#define NSTG 3

template<int BM, int BN, bool BTRANS>
struct SmemSizes {
    static constexpr int AWORDS = BM * BK;
    static constexpr int BSTNN  = BN + 8;
    static constexpr int BWORDS = BTRANS ? BN * BK : BK * BSTNN;
    static constexpr int STW    = AWORDS + BWORDS;     // words per stage
    static constexpr int BYTES  = NSTG * STW * 4;
};

template<int BM, int BN, int WM, int WN, bool BTRANS, bool RNDA, bool RNDOUT, bool SMAX>
__global__ __launch_bounds__(256, 2) void gemm_tc(
    const float* __restrict__ A, long long sA, int lda,
    const float* __restrict__ B, long long sB, int ldb,
    float* __restrict__ C, long long sC, int ldc,
    int Kloop,
    const float* __restrict__ bias, float scale,
    const float* __restrict__ lens,
    const float* __restrict__ klim,
    int nsplit, long long sSplit)
{
    constexpr int WCOLS = BN / WN;
    constexpr int MT  = WM / 16;
    constexpr int NTt = WN / 8;
    constexpr int NJ  = NTt / 2;
    constexpr int AWORDS = SmemSizes<BM, BN, BTRANS>::AWORDS;
    constexpr int BSTNN  = SmemSizes<BM, BN, BTRANS>::BSTNN;
    constexpr int STW    = SmemSizes<BM, BN, BTRANS>::STW;

    extern __shared__ unsigned smem_dyn[];
    const unsigned sbase = (unsigned)__cvta_generic_to_shared(smem_dyn);

    const int bz = blockIdx.z;
    const int b  = bz / nsplit;
    const int ks = bz % nsplit;

    const float* Ab = A + (long long)b * sA + (long long)ks * Kloop;
    const float* Bb;
    if (BTRANS) Bb = B + (long long)b * sB + (long long)ks * Kloop;
    else        Bb = B + (long long)b * sB + (long long)ks * Kloop * ldb;
    float* Cb = C + (long long)b * sC + (long long)ks * sSplit;

    const int m0 = blockIdx.y * BM;
    const int n0 = blockIdx.x * BN;

    float maskLen = 3.0e38f;
    if (lens) {
        float L = lens[b];
        scale = rsqrtf(L);
        maskLen = L;
        if ((float)n0 >= maskLen) return;
    }

    int nIter = Kloop / BK;
    if (klim) {
        int eff = (int)klim[b] - ks * Kloop;
        eff = eff < 0 ? 0 : (eff > Kloop ? Kloop : eff);
        nIter = (eff + BK - 1) / BK;
    }

    const int tid  = threadIdx.x;
    const int lane = tid & 31;
    const int wid  = tid >> 5;
    const int wm   = wid / WCOLS;
    const int wn   = wid % WCOLS;
    const int g    = lane >> 2;
    const int t4   = lane & 3;
    const int l7   = lane & 7;
    const int lr15 = lane & 15;
    const int hb   = lane >> 4;
    const int qb   = (lane >> 3) & 1;

    const int ar = tid >> 3;
    const int aq = tid & 7;

    auto loadA = [&](int s, int k0) {
        const unsigned abase = sbase + (s * STW) * 4;
#pragma unroll
        for (int i = 0; i < BM / 32; i++) {
            const int row = ar + 32 * i;
            cpa16s(abase + (row * BK + ((aq ^ (row & 7)) << 2)) * 4,
                   Ab + (long long)(m0 + row) * lda + k0 + (aq << 2));
        }
    };
    auto loadB = [&](int s, int k0) {
        const unsigned bbase = sbase + (s * STW + AWORDS) * 4;
        if (BTRANS) {
#pragma unroll
            for (int i = 0; i < BN / 32; i++) {
                const int row = ar + 32 * i;
                cpa16s(bbase + (row * BK + ((aq ^ (row & 7)) << 2)) * 4,
                       Bb + (long long)(n0 + row) * ldb + k0 + (aq << 2));
            }
        } else {
            constexpr int QPR = BN / 4;
            constexpr int RPP = 256 / QPR;
            const int bk = tid / QPR;
            const int bq = tid % QPR;
#pragma unroll
            for (int i = 0; i < BK / RPP; i++) {
                const int krow = bk + RPP * i;
                cpa16s(bbase + (krow * BSTNN + bq * 4) * 4,
                       Bb + (long long)(k0 + krow) * ldb + n0 + bq * 4);
            }
        }
    };

    unsigned aRowOff[MT];
#pragma unroll
    for (int i = 0; i < MT; i++)
        aRowOff[i] = (wm * WM + i * 16 + lr15) * BK * 4;
    unsigned bRowOff[NJ];
    if (BTRANS) {
#pragma unroll
        for (int jj = 0; jj < NJ; jj++)
            bRowOff[jj] = (wn * WN + jj * 16 + hb * 8 + l7) * BK * 4;
    }

    float acc[MT][NTt][4];
#pragma unroll
    for (int i = 0; i < MT; i++)
#pragma unroll
        for (int j = 0; j < NTt; j++)
#pragma unroll
            for (int q = 0; q < 4; q++) acc[i][j][q] = 0.f;

    if (nIter > 0) {
        loadA(0, 0);
        loadB(0, 0);
        cp_commit();
        if (nIter > 1) { loadA(1, BK); loadB(1, BK); }
        cp_commit();

        int cb = 0;
        for (int it = 0; it < nIter; it++) {
            if (it + 2 < nIter) {
                const int nbuf = (cb == 0) ? 2 : cb - 1;
                loadA(nbuf, (it + 2) * BK);
                loadB(nbuf, (it + 2) * BK);
            }
            cp_commit();
            cp_wait<2>();
            __syncthreads();

            const unsigned aSt = sbase + (cb * STW) * 4;
            const unsigned bSt = aSt + AWORDS * 4;
            const unsigned* BsNN = smem_dyn + cb * STW + AWORDS;

#pragma unroll
            for (int kss = 0; kss < BK / 8; kss++) {
                const int q0 = kss * 2;
                unsigned af[MT][4];
#pragma unroll
                for (int i = 0; i < MT; i++) {
                    ldsm_x4(af[i][0], af[i][1], af[i][2], af[i][3],
                            aSt + aRowOff[i] + (unsigned)((((q0 + hb) ^ l7)) << 4));
                    if (RNDA) {
                        af[i][0] = rnd13(af[i][0]); af[i][1] = rnd13(af[i][1]);
                        af[i][2] = rnd13(af[i][2]); af[i][3] = rnd13(af[i][3]);
                    }
                }
                unsigned bf[NTt][2];
                if (BTRANS) {
#pragma unroll
                    for (int jj = 0; jj < NJ; jj++) {
                        unsigned w0, w1, w2, w3;
                        ldsm_x4(w0, w1, w2, w3,
                                bSt + bRowOff[jj] + (unsigned)((((q0 + qb) ^ l7)) << 4));
                        bf[2 * jj][0]     = w0;
                        bf[2 * jj][1]     = w1;
                        bf[2 * jj + 1][0] = w2;
                        bf[2 * jj + 1][1] = w3;
                    }
                } else {
                    const int kb = kss * 8;
#pragma unroll
                    for (int j = 0; j < NTt; j++) {
                        const int n = wn * WN + j * 8 + g;
                        bf[j][0] = BsNN[(kb + t4)     * BSTNN + n];
                        bf[j][1] = BsNN[(kb + t4 + 4) * BSTNN + n];
                    }
                }
#pragma unroll
                for (int i = 0; i < MT; i++)
#pragma unroll
                    for (int j = 0; j < NTt; j++)
                        mma_tf32(acc[i][j], af[i], bf[j]);
            }
            __syncthreads();
            cb = (cb == 2) ? 0 : cb + 1;
        }
    }

    // ---- epilogue ----
    if constexpr (SMAX) {
        // fused row softmax: BM=128 rows, BN=64=N full rows in-CTA.
        constexpr int SST = 72;               // padded row stride (words)
        float* Ss = (float*)smem_dyn;         // 128*72*4 = 36 KB < pipeline smem
        __syncthreads();                      // stage buffers dead; reuse
#pragma unroll
        for (int i = 0; i < MT; i++) {
            const int r0 = wm * WM + i * 16 + g;
#pragma unroll
            for (int j = 0; j < NTt; j++) {
                const int c = wn * WN + j * 8 + 2 * t4;
                Ss[r0 * SST + c]           = acc[i][j][0] * scale;
                Ss[r0 * SST + c + 1]       = acc[i][j][1] * scale;
                Ss[(r0 + 8) * SST + c]     = acc[i][j][2] * scale;
                Ss[(r0 + 8) * SST + c + 1] = acc[i][j][3] * scale;
            }
        }
        __syncthreads();
        // warp-per-row softmax, identical order to softmax_rows (c=lane, lane+32)
#pragma unroll
        for (int ii = 0; ii < 16; ii++) {
            const int r = wid * 16 + ii;
            float* p = Ss + r * SST;
            const float v0 = p[lane];
            const float v1 = p[lane + 32];
            float m = fmaxf(fmaxf(-3.0e38f, v0), v1);
#pragma unroll
            for (int o = 16; o; o >>= 1) m = fmaxf(m, __shfl_xor_sync(0xffffffffu, m, o));
            const float e0 = __expf(v0 - m);
            const float e1 = __expf(v1 - m);
            float s = e0 + e1;
#pragma unroll
            for (int o = 16; o; o >>= 1) s += __shfl_xor_sync(0xffffffffu, s, o);
            const float inv = 1.f / s;
            p[lane]      = roundtf(e0 * inv);
            p[lane + 32] = roundtf(e1 * inv);
        }
        __syncthreads();
        // coalesced store: 128 rows x 64 cols
#pragma unroll
        for (int i = 0; i < (BM * BN) / (256 * 4); i++) {
            const int idx = tid + i * 256;
            const int r = idx >> 4;
            const int q = idx & 15;
            *(float4*)(Cb + (long long)(m0 + r) * ldc + n0 + q * 4) =
                *(const float4*)(Ss + r * SST + q * 4);
        }
    } else {
#pragma unroll
        for (int i = 0; i < MT; i++) {
            const int mrow = m0 + wm * WM + i * 16 + g;
#pragma unroll
            for (int j = 0; j < NTt; j++) {
                const int ncol = n0 + wn * WN + j * 8 + 2 * t4;
                float b0 = bias ? bias[ncol]     : 0.f;
                float b1 = bias ? bias[ncol + 1] : 0.f;
                float v0 = acc[i][j][0] * scale + b0;
                float v1 = acc[i][j][1] * scale + b1;
                float v2 = acc[i][j][2] * scale + b0;
                float v3 = acc[i][j][3] * scale + b1;
                if (lens) {
                    if ((float)ncol     >= maskLen) { v0 = -1e9f; v2 = -1e9f; }
                    if ((float)(ncol+1) >= maskLen) { v1 = -1e9f; v3 = -1e9f; }
                }
                if (RNDOUT) {
                    v0 = roundtf(v0); v1 = roundtf(v1);
                    v2 = roundtf(v2); v3 = roundtf(v3);
                }
                *(float2*)(Cb + (long long)mrow * ldc + ncol)       = make_float2(v0, v1);
                *(float2*)(Cb + (long long)(mrow + 8) * ldc + ncol) = make_float2(v2, v3);
            }
        }
    }
}

// ---------------- weight prep ---------------------------------------------
__global__ void prep_weights(const float* K1w, const float* V1w, const float* Qw,
                             const float* Q1w, const float* Kw, const float* Vw,
                             float* wf, float* wr2)
{
    const int seg = blockIdx.y;
    const float* src;
    switch (seg) {
        case 0: src = K1w; break; case 1: src = V1w; break;
        case 2: src = Qw;  break; case 3: src = Q1w; break;
        case 4: src = Kw;  break; default: src = Vw; break;
    }
    const int i = blockIdx.x * blockDim.x + threadIdx.x;
    const float v = roundtf(src[i]);
    if (seg < 3) wf[seg * HH * HH + i] = v;
    else         wr2[(seg - 3) * HH * HH + i] = v;
}

__global__ void fuse_bias(const float* K1b, const float* V1b, const float* Qb,
                          float* b3)
{
    const int j = blockIdx.x * blockDim.x + threadIdx.x;
    b3[j] = (j < 256) ? K1b[j] : (j < 512) ? V1b[j - 256] : Qb[j - 512];
}

// ---------------- split-K reduce ------------------------------------------
__global__ void reduce_splits(const float* __restrict__ part,
                              float* __restrict__ out,
                              int n, long long stride)
{
    const int i = blockIdx.x * blockDim.x + threadIdx.x;
    if (i >= n) return;
    float s = 0.f;
#pragma unroll
    for (int k = 0; k < NSPLIT; k++) s += part[(long long)k * stride + i];
    out[i] = roundtf(s);
}

// ---------------- softmax over rows (warp per row), in place -------------
__global__ void softmax_rows(float* __restrict__ x, int rows, int cols,
                             const float* __restrict__ lens, int rpb)
{
    const int row = blockIdx.x * (blockDim.x / 32) + (threadIdx.x / 32);
    if (row >= rows) return;
    const int lane = threadIdx.x & 31;
    float* p = x + (long long)row * cols;

    int L = cols;
    if (lens) L = (int)lens[row / rpb];

    float m = -3.0e38f;
    for (int c = lane; c < L; c += 32) m = fmaxf(m, p[c]);
#pragma unroll
    for (int o = 16; o; o >>= 1) m = fmaxf(m, __shfl_xor_sync(0xffffffffu, m, o));

    float s = 0.f;
    for (int c = lane; c < L; c += 32) {
        float e = __expf(p[c] - m);
        p[c] = e;
        s += e;
    }
#pragma unroll
    for (int o = 16; o; o >>= 1) s += __shfl_xor_sync(0xffffffffu, s, o);

    const float inv = 1.f / s;
    for (int c = lane; c < L; c += 32) p[c] = roundtf(p[c] * inv);
    for (int c = L + lane; c < cols; c += 32) p[c] = 0.f;
}

// ---------------- launch helper -------------------------------------------
template<int BM, int BN, int WM, int WN, bool BTRANS, bool RNDA, bool RNDOUT,
         bool SMAX = false>
static void launch_gemm(dim3 grid,
                        const float* A, long long sA, int lda,
                        const float* B, long long sB, int ldb,
                        float* C, long long sC, int ldc,
                        int Kloop,
                        const float* bias, float scale,
                        const float* lens, const float* klim,
                        int nsplit, long long sSplit)
{
    constexpr int PIPE = SmemSizes<BM, BN, BTRANS>::BYTES;
    constexpr int SMEM = (SMAX && PIPE < BM * 72 * 4) ? BM * 72 * 4 : PIPE;
    cudaFuncSetAttribute(gemm_tc<BM, BN, WM, WN, BTRANS, RNDA, RNDOUT, SMAX>,
                         cudaFuncAttributeMaxDynamicSharedMemorySize, SMEM);
    gemm_tc<BM, BN, WM, WN, BTRANS, RNDA, RNDOUT, SMAX><<<grid, 256, SMEM>>>(
        A, sA, lda, B, sB, ldb, C, sC, ldc, Kloop, bias, scale, lens, klim,
        nsplit, sSplit);
}

// ---------------- launch ---------------------------------------------------
extern "C" void kernel_launch(void* const* d_in, const int* in_sizes, int n_in,
                              void* d_out, int out_size)
{
    const float* hs    = (const float*)d_in[0];
    const float* proto = (const float*)d_in[1];
    const float* lens  = (const float*)d_in[2];
    // d_in[3] = mask (bool) — unused; reconstructed from lens
    const float* Q1w = (const float*)d_in[4];
    const float* Q1b = (const float*)d_in[5];
    const float* K1w = (const float*)d_in[6];
    const float* K1b = (const float*)d_in[7];
    const float* V1w = (const float*)d_in[8];
    const float* V1b = (const float*)d_in[9];
    const float* Qw  = (const float*)d_in[10];
    const float* Qb  = (const float*)d_in[11];
    const float* Kw  = (const float*)d_in[12];
    const float* Kb  = (const float*)d_in[13];
    const float* Vw  = (const float*)d_in[14];
    const float* Vb  = (const float*)d_in[15];
    float* out = (float*)d_out;

    float *kvq, *q1, *pf, *pfp, *k2, *v2, *s1, *wf, *wr2, *b3;
    cudaGetSymbolAddress((void**)&kvq, g_kvq);
    cudaGetSymbolAddress((void**)&q1, g_q1);
    cudaGetSymbolAddress((void**)&pf, g_pf);
    cudaGetSymbolAddress((void**)&pfp, g_pfp);
    cudaGetSymbolAddress((void**)&k2, g_k2);
    cudaGetSymbolAddress((void**)&v2, g_v2);
    cudaGetSymbolAddress((void**)&s1, g_s1);
    cudaGetSymbolAddress((void**)&wf, g_wf);
    cudaGetSymbolAddress((void**)&wr2, g_wr2);
    cudaGetSymbolAddress((void**)&b3, g_b3);
    float* s2 = s1;   // safe reuse: s1 fully consumed before scores2 written

    const int BT = BB * TT;        // 65536
    const int BP = BB * PP;        // 1024
    const long long TH = (long long)TT * HH;
    const long long PH = (long long)PP * HH;
    const long long PT = (long long)PP * TT;
    const long long TP = (long long)TT * PP;
    const long long TF = (long long)TT * NF;

    // weight prep
    prep_weights<<<dim3(HH * HH / 256, 6), 256>>>(K1w, V1w, Qw, Q1w, Kw, Vw, wf, wr2);
    fuse_bias<<<3, 256>>>(K1b, V1b, Qb, b3);
    const float* rQ1w = wr2 + 0 * HH * HH;
    const float* rKw  = wr2 + 1 * HH * HH;
    const float* rVw  = wr2 + 2 * HH * HH;

    // q1 = proto @ Q1_w^T + Q1_b                    [64, 256]
    launch_gemm<64, 128, 32, 32, true, true, true>(dim3(HH / 128, 1, 1),
        proto, 0, HH, rQ1w, 0, HH, q1, 0, HH, HH, Q1b, 1.f, nullptr, nullptr, 1, 0);

    // fused k1|v1|q2 over all tokens                [65536, 768]
    launch_gemm<128, 128, 64, 32, true, true, true>(dim3(NF / 128, BT / 128, 1),
        hs, 0, HH, wf, 0, HH, kvq, 0, NF, HH, b3, 1.f, nullptr, nullptr, 1, 0);

    // scores1[b,p,t] = q1 . k1 * rsqrt(len_b); masked tiles skipped
    launch_gemm<64, 128, 32, 32, true, false, false>(dim3(TT / 128, 1, BB),
        q1, 0, HH, kvq + 0, TF, NF, s1, PT, TT, HH, nullptr, 1.f, lens, nullptr, 1, 0);

    softmax_rows<<<BP / 8, 256>>>(s1, BP, TT, lens, PP);

    // pf[b] = attn1 @ v1   (split-K x8, per-batch K limit) [64, 256]/batch
    launch_gemm<64, 64, 32, 16, false, false, false>(dim3(HH / 64, 1, BB * NSPLIT),
        s1, PT, TT, kvq + 256, TF, NF, pfp, PH, HH, TT / NSPLIT,
        nullptr, 1.f, nullptr, lens, NSPLIT, (long long)BB * PP * HH);
    reduce_splits<<<(BB * PP * HH + 255) / 256, 256>>>(
        pfp, pf, BB * PP * HH, (long long)BB * PP * HH);

    // k2 / v2 = pf @ {K,V}_w^T + b                  [1024, 256]
    launch_gemm<64, 128, 32, 32, true, false, true>(dim3(HH / 128, BP / 64, 1),
        pf, 0, HH, rKw, 0, HH, k2, 0, HH, HH, Kb, 1.f, nullptr, nullptr, 1, 0);
    launch_gemm<64, 128, 32, 32, true, false, true>(dim3(HH / 128, BP / 64, 1),
        pf, 0, HH, rVw, 0, HH, v2, 0, HH, HH, Vb, 1.f, nullptr, nullptr, 1, 0);

    // scores2 + fused softmax2 (SMAX epilogue; rows fully in-CTA, N=P=64)
    launch_gemm<128, 64, 32, 32, true, false, false, true>(
        dim3(PP / 64, TT / 128, BB),
        kvq + 512, TF, NF, k2, PH, HH, s2, TP, PP, HH,
        nullptr, 0.125f, nullptr, nullptr, 1, 0);

    // out[b] = attn2 @ v2                           [4096, 256] per batch
    launch_gemm<128, 128, 64, 32, false, false, false>(dim3(HH / 128, TT / 128, BB),
        s2, TP, PP, v2, PH, HH, out, TH, HH, PP, nullptr, 1.f, nullptr, nullptr, 1, 0);
}

// round 15
// speedup vs baseline: 1.1049x; 1.0365x over previous
#include <cuda_runtime.h>
#include <cuda_bf16.h>
#include <math.h>

// Problem dims (fixed by the dataset)
#define BB 16
#define TT 4096
#define HH 256
#define PP 64

#define NSPLIT 8   // split-K factor for the pf GEMM
#define NF 768     // fused k1|v1|q2 width
#define NKV 512    // fused k2|v2 width

// ---------------- scratch (no allocation allowed) ----------------
__device__ float g_kvq[BB * TT * NF];  // fused [k1 | v1 | q2], 192 MB
__device__ float g_q1[PP * HH];
__device__ float g_pf[BB * PP * HH];
__device__ float g_pfp[NSPLIT * BB * PP * HH];  // split-K partials (8 MB)
__device__ float g_kv2[BB * PP * NKV]; // fused [k2 | v2], 2 MB
__device__ float g_s1[BB * PP * TT];   // 16 MB; reused as s2 (stream-ordered)
__device__ float g_wf[NF * HH];        // fused rounded weights [K1w;V1w;Qw]
__device__ float g_wkv[NKV * HH];      // fused rounded weights [Kw;Vw]
__device__ float g_wr2[HH * HH];       // rounded Q1w
__device__ float g_b3[NF];             // fused biases [K1b;V1b;Qb]
__device__ float g_b2[NKV];            // fused biases [Kb;Vb]

// ---------------- helpers ------------------------------------------------
__device__ __forceinline__ void mma_tf32(float* c, const unsigned* a, const unsigned* b) {
    asm("mma.sync.aligned.m16n8k8.row.col.f32.tf32.tf32.f32 "
        "{%0,%1,%2,%3},{%4,%5,%6,%7},{%8,%9},{%0,%1,%2,%3};"
        : "+f"(c[0]), "+f"(c[1]), "+f"(c[2]), "+f"(c[3])
        : "r"(a[0]), "r"(a[1]), "r"(a[2]), "r"(a[3]), "r"(b[0]), "r"(b[1]));
}

// RNA round to the tf32 grid. MMA truncation of such a value is the identity.
__device__ __forceinline__ unsigned rnd13(unsigned u) { return u + 0x1000u; }
__device__ __forceinline__ float roundtf(float f) {
    unsigned u = __float_as_uint(f);
    u = (u + 0x1000u) & 0xFFFFE000u;
    return __uint_as_float(u);
}

__device__ __forceinline__ void ldsm_x4(unsigned& r0, unsigned& r1,
                                        unsigned& r2, unsigned& r3, unsigned addr) {
    asm volatile("ldmatrix.sync.aligned.m8n8.x4.shared.b16 {%0,%1,%2,%3}, [%4];"
                 : "=r"(r0), "=r"(r1), "=r"(r2), "=r"(r3) : "r"(addr));
}

__device__ __forceinline__ void cpa16s(unsigned dst, const void* src) {
    asm volatile("cp.async.cg.shared.global [%0], [%1], 16;" :: "r"(dst), "l"(src));
}
__device__ __forceinline__ void cp_commit() {
    asm volatile("cp.async.commit_group;");
}
template<int N>
__device__ __forceinline__ void cp_wait() {
    asm volatile("cp.async.wait_group %0;" :: "n"(N));
}

// ---------------- TF32 tensor-core GEMM, 3-stage cp.async + ldmatrix -----
// One barrier per mainloop iteration: wait<1> -> sync -> prefetch(it+2) ->
// compute(cb). The prefetch buffer (cb+2)%3 == (cb-1)%3 was last read in
// iteration it-1, which every warp finished before passing this barrier.
#define BK 32
#define NSTG 3

template<int BM, int BN, bool BTRANS>
struct SmemSizes {
    static constexpr int AWORDS = BM * BK;
    static constexpr int BSTNN  = BN + 8;
    static constexpr int BWORDS = BTRANS ? BN * BK : BK * BSTNN;
    static constexpr int STW    = AWORDS + BWORDS;     // words per stage
    static constexpr int BYTES  = NSTG * STW * 4;
};

template<int BM, int BN, int WM, int WN, bool BTRANS, bool RNDA, bool RNDOUT, bool SMAX>
__global__ __launch_bounds__(256, 2) void gemm_tc(
    const float* __restrict__ A, long long sA, int lda,
    const float* __restrict__ B, long long sB, int ldb,
    float* __restrict__ C, long long sC, int ldc,
    int Kloop,
    const float* __restrict__ bias, float scale,
    const float* __restrict__ lens,
    const float* __restrict__ klim,
    int nsplit, long long sSplit)
{
    constexpr int WCOLS = BN / WN;
    constexpr int MT  = WM / 16;
    constexpr int NTt = WN / 8;
    constexpr int NJ  = NTt / 2;
    constexpr int AWORDS = SmemSizes<BM, BN, BTRANS>::AWORDS;
    constexpr int BSTNN  = SmemSizes<BM, BN, BTRANS>::BSTNN;
    constexpr int STW    = SmemSizes<BM, BN, BTRANS>::STW;

    extern __shared__ unsigned smem_dyn[];
    const unsigned sbase = (unsigned)__cvta_generic_to_shared(smem_dyn);

    const int bz = blockIdx.z;
    const int b  = bz / nsplit;
    const int ks = bz % nsplit;

    const float* Ab = A + (long long)b * sA + (long long)ks * Kloop;
    const float* Bb;
    if (BTRANS) Bb = B + (long long)b * sB + (long long)ks * Kloop;
    else        Bb = B + (long long)b * sB + (long long)ks * Kloop * ldb;
    float* Cb = C + (long long)b * sC + (long long)ks * sSplit;

    const int m0 = blockIdx.y * BM;
    const int n0 = blockIdx.x * BN;

    float maskLen = 3.0e38f;
    if (lens) {
        float L = lens[b];
        scale = rsqrtf(L);
        maskLen = L;
        if ((float)n0 >= maskLen) return;
    }

    int nIter = Kloop / BK;
    if (klim) {
        int eff = (int)klim[b] - ks * Kloop;
        eff = eff < 0 ? 0 : (eff > Kloop ? Kloop : eff);
        nIter = (eff + BK - 1) / BK;
    }

    const int tid  = threadIdx.x;
    const int lane = tid & 31;
    const int wid  = tid >> 5;
    const int wm   = wid / WCOLS;
    const int wn   = wid % WCOLS;
    const int g    = lane >> 2;
    const int t4   = lane & 3;
    const int l7   = lane & 7;
    const int lr15 = lane & 15;
    const int hb   = lane >> 4;
    const int qb   = (lane >> 3) & 1;

    const int ar = tid >> 3;
    const int aq = tid & 7;

    auto loadA = [&](int s, int k0) {
        const unsigned abase = sbase + (s * STW) * 4;
#pragma unroll
        for (int i = 0; i < BM / 32; i++) {
            const int row = ar + 32 * i;
            cpa16s(abase + (row * BK + ((aq ^ (row & 7)) << 2)) * 4,
                   Ab + (long long)(m0 + row) * lda + k0 + (aq << 2));
        }
    };
    auto loadB = [&](int s, int k0) {
        const unsigned bbase = sbase + (s * STW + AWORDS) * 4;
        if (BTRANS) {
#pragma unroll
            for (int i = 0; i < BN / 32; i++) {
                const int row = ar + 32 * i;
                cpa16s(bbase + (row * BK + ((aq ^ (row & 7)) << 2)) * 4,
                       Bb + (long long)(n0 + row) * ldb + k0 + (aq << 2));
            }
        } else {
            constexpr int QPR = BN / 4;
            constexpr int RPP = 256 / QPR;
            const int bk = tid / QPR;
            const int bq = tid % QPR;
#pragma unroll
            for (int i = 0; i < BK / RPP; i++) {
                const int krow = bk + RPP * i;
                cpa16s(bbase + (krow * BSTNN + bq * 4) * 4,
                       Bb + (long long)(k0 + krow) * ldb + n0 + bq * 4);
            }
        }
    };

    unsigned aRowOff[MT];
#pragma unroll
    for (int i = 0; i < MT; i++)
        aRowOff[i] = (wm * WM + i * 16 + lr15) * BK * 4;
    unsigned bRowOff[NJ];
    if (BTRANS) {
#pragma unroll
        for (int jj = 0; jj < NJ; jj++)
            bRowOff[jj] = (wn * WN + jj * 16 + hb * 8 + l7) * BK * 4;
    }

    float acc[MT][NTt][4];
#pragma unroll
    for (int i = 0; i < MT; i++)
#pragma unroll
        for (int j = 0; j < NTt; j++)
#pragma unroll
            for (int q = 0; q < 4; q++) acc[i][j][q] = 0.f;

    if (nIter > 0) {
        loadA(0, 0);
        loadB(0, 0);
        cp_commit();
        if (nIter > 1) { loadA(1, BK); loadB(1, BK); }
        cp_commit();

        int cb = 0;
        for (int it = 0; it < nIter; it++) {
            cp_wait<1>();
            __syncthreads();

            if (it + 2 < nIter) {
                const int nbuf = (cb == 0) ? 2 : cb - 1;   // (cb+2) mod 3
                loadA(nbuf, (it + 2) * BK);
                loadB(nbuf, (it + 2) * BK);
            }
            cp_commit();          // may be empty (keeps FIFO uniform)

            const unsigned aSt = sbase + (cb * STW) * 4;
            const unsigned bSt = aSt + AWORDS * 4;
            const unsigned* BsNN = smem_dyn + cb * STW + AWORDS;

#pragma unroll
            for (int kss = 0; kss < BK / 8; kss++) {
                const int q0 = kss * 2;
                unsigned af[MT][4];
#pragma unroll
                for (int i = 0; i < MT; i++) {
                    ldsm_x4(af[i][0], af[i][1], af[i][2], af[i][3],
                            aSt + aRowOff[i] + (unsigned)((((q0 + hb) ^ l7)) << 4));
                    if (RNDA) {
                        af[i][0] = rnd13(af[i][0]); af[i][1] = rnd13(af[i][1]);
                        af[i][2] = rnd13(af[i][2]); af[i][3] = rnd13(af[i][3]);
                    }
                }
                unsigned bf[NTt][2];
                if (BTRANS) {
#pragma unroll
                    for (int jj = 0; jj < NJ; jj++) {
                        unsigned w0, w1, w2, w3;
                        ldsm_x4(w0, w1, w2, w3,
                                bSt + bRowOff[jj] + (unsigned)((((q0 + qb) ^ l7)) << 4));
                        bf[2 * jj][0]     = w0;
                        bf[2 * jj][1]     = w1;
                        bf[2 * jj + 1][0] = w2;
                        bf[2 * jj + 1][1] = w3;
                    }
                } else {
                    const int kb = kss * 8;
#pragma unroll
                    for (int j = 0; j < NTt; j++) {
                        const int n = wn * WN + j * 8 + g;
                        bf[j][0] = BsNN[(kb + t4)     * BSTNN + n];
                        bf[j][1] = BsNN[(kb + t4 + 4) * BSTNN + n];
                    }
                }
#pragma unroll
                for (int i = 0; i < MT; i++)
#pragma unroll
                    for (int j = 0; j < NTt; j++)
                        mma_tf32(acc[i][j], af[i], bf[j]);
            }
            cb = (cb == 2) ? 0 : cb + 1;
        }
    }

    // ---- epilogue ----
    if constexpr (SMAX) {
        // fused row softmax: BM=128 rows, BN=64=N full rows in-CTA.
        constexpr int SST = 72;
        float* Ss = (float*)smem_dyn;
        __syncthreads();                      // stage buffers dead; reuse
#pragma unroll
        for (int i = 0; i < MT; i++) {
            const int r0 = wm * WM + i * 16 + g;
#pragma unroll
            for (int j = 0; j < NTt; j++) {
                const int c = wn * WN + j * 8 + 2 * t4;
                Ss[r0 * SST + c]           = acc[i][j][0] * scale;
                Ss[r0 * SST + c + 1]       = acc[i][j][1] * scale;
                Ss[(r0 + 8) * SST + c]     = acc[i][j][2] * scale;
                Ss[(r0 + 8) * SST + c + 1] = acc[i][j][3] * scale;
            }
        }
        __syncthreads();
#pragma unroll
        for (int ii = 0; ii < 16; ii++) {
            const int r = wid * 16 + ii;
            float* p = Ss + r * SST;
            const float v0 = p[lane];
            const float v1 = p[lane + 32];
            float m = fmaxf(fmaxf(-3.0e38f, v0), v1);
#pragma unroll
            for (int o = 16; o; o >>= 1) m = fmaxf(m, __shfl_xor_sync(0xffffffffu, m, o));
            const float e0 = __expf(v0 - m);
            const float e1 = __expf(v1 - m);
            float s = e0 + e1;
#pragma unroll
            for (int o = 16; o; o >>= 1) s += __shfl_xor_sync(0xffffffffu, s, o);
            const float inv = 1.f / s;
            p[lane]      = roundtf(e0 * inv);
            p[lane + 32] = roundtf(e1 * inv);
        }
        __syncthreads();
#pragma unroll
        for (int i = 0; i < (BM * BN) / (256 * 4); i++) {
            const int idx = tid + i * 256;
            const int r = idx >> 4;
            const int q = idx & 15;
            *(float4*)(Cb + (long long)(m0 + r) * ldc + n0 + q * 4) =
                *(const float4*)(Ss + r * SST + q * 4);
        }
    } else {
#pragma unroll
        for (int i = 0; i < MT; i++) {
            const int mrow = m0 + wm * WM + i * 16 + g;
#pragma unroll
            for (int j = 0; j < NTt; j++) {
                const int ncol = n0 + wn * WN + j * 8 + 2 * t4;
                float b0 = bias ? bias[ncol]     : 0.f;
                float b1 = bias ? bias[ncol + 1] : 0.f;
                float v0 = acc[i][j][0] * scale + b0;
                float v1 = acc[i][j][1] * scale + b1;
                float v2 = acc[i][j][2] * scale + b0;
                float v3 = acc[i][j][3] * scale + b1;
                if (lens) {
                    if ((float)ncol     >= maskLen) { v0 = -1e9f; v2 = -1e9f; }
                    if ((float)(ncol+1) >= maskLen) { v1 = -1e9f; v3 = -1e9f; }
                }
                if (RNDOUT) {
                    v0 = roundtf(v0); v1 = roundtf(v1);
                    v2 = roundtf(v2); v3 = roundtf(v3);
                }
                *(float2*)(Cb + (long long)mrow * ldc + ncol)       = make_float2(v0, v1);
                *(float2*)(Cb + (long long)(mrow + 8) * ldc + ncol) = make_float2(v2, v3);
            }
        }
    }
}

// ---------------- weight prep ---------------------------------------------
// seg 0-2 -> wf (K1w,V1w,Qw); seg 3 -> wr2 (Q1w); seg 4,5 -> wkv (Kw,Vw)
__global__ void prep_weights(const float* K1w, const float* V1w, const float* Qw,
                             const float* Q1w, const float* Kw, const float* Vw,
                             float* wf, float* wr2, float* wkv)
{
    const int seg = blockIdx.y;
    const float* src;
    switch (seg) {
        case 0: src = K1w; break; case 1: src = V1w; break;
        case 2: src = Qw;  break; case 3: src = Q1w; break;
        case 4: src = Kw;  break; default: src = Vw; break;
    }
    const int i = blockIdx.x * blockDim.x + threadIdx.x;
    const float v = roundtf(src[i]);
    if (seg < 3)      wf[seg * HH * HH + i] = v;
    else if (seg == 3) wr2[i] = v;
    else              wkv[(seg - 4) * HH * HH + i] = v;
}

// j in [0,1280): 0-767 -> b3 [K1b;V1b;Qb]; 768-1279 -> b2 [Kb;Vb]
__global__ void fuse_bias(const float* K1b, const float* V1b, const float* Qb,
                          const float* Kb, const float* Vb,
                          float* b3, float* b2)
{
    const int j = blockIdx.x * blockDim.x + threadIdx.x;
    if (j < 256)        b3[j] = K1b[j];
    else if (j < 512)   b3[j] = V1b[j - 256];
    else if (j < 768)   b3[j] = Qb[j - 512];
    else if (j < 1024)  b2[j - 768] = Kb[j - 768];
    else                b2[j - 768] = Vb[j - 1024];
}

// ---------------- split-K reduce ------------------------------------------
__global__ void reduce_splits(const float* __restrict__ part,
                              float* __restrict__ out,
                              int n, long long stride)
{
    const int i = blockIdx.x * blockDim.x + threadIdx.x;
    if (i >= n) return;
    float s = 0.f;
#pragma unroll
    for (int k = 0; k < NSPLIT; k++) s += part[(long long)k * stride + i];
    out[i] = roundtf(s);
}

// ---------------- softmax over rows (warp per row), in place -------------
__global__ void softmax_rows(float* __restrict__ x, int rows, int cols,
                             const float* __restrict__ lens, int rpb)
{
    const int row = blockIdx.x * (blockDim.x / 32) + (threadIdx.x / 32);
    if (row >= rows) return;
    const int lane = threadIdx.x & 31;
    float* p = x + (long long)row * cols;

    int L = cols;
    if (lens) L = (int)lens[row / rpb];

    float m = -3.0e38f;
    for (int c = lane; c < L; c += 32) m = fmaxf(m, p[c]);
#pragma unroll
    for (int o = 16; o; o >>= 1) m = fmaxf(m, __shfl_xor_sync(0xffffffffu, m, o));

    float s = 0.f;
    for (int c = lane; c < L; c += 32) {
        float e = __expf(p[c] - m);
        p[c] = e;
        s += e;
    }
#pragma unroll
    for (int o = 16; o; o >>= 1) s += __shfl_xor_sync(0xffffffffu, s, o);

    const float inv = 1.f / s;
    for (int c = lane; c < L; c += 32) p[c] = roundtf(p[c] * inv);
    for (int c = L + lane; c < cols; c += 32) p[c] = 0.f;
}

// ---------------- launch helper -------------------------------------------
template<int BM, int BN, int WM, int WN, bool BTRANS, bool RNDA, bool RNDOUT,
         bool SMAX = false>
static void launch_gemm(dim3 grid,
                        const float* A, long long sA, int lda,
                        const float* B, long long sB, int ldb,
                        float* C, long long sC, int ldc,
                        int Kloop,
                        const float* bias, float scale,
                        const float* lens, const float* klim,
                        int nsplit, long long sSplit)
{
    constexpr int PIPE = SmemSizes<BM, BN, BTRANS>::BYTES;
    constexpr int SMEM = (SMAX && PIPE < BM * 72 * 4) ? BM * 72 * 4 : PIPE;
    cudaFuncSetAttribute(gemm_tc<BM, BN, WM, WN, BTRANS, RNDA, RNDOUT, SMAX>,
                         cudaFuncAttributeMaxDynamicSharedMemorySize, SMEM);
    gemm_tc<BM, BN, WM, WN, BTRANS, RNDA, RNDOUT, SMAX><<<grid, 256, SMEM>>>(
        A, sA, lda, B, sB, ldb, C, sC, ldc, Kloop, bias, scale, lens, klim,
        nsplit, sSplit);
}

// ---------------- launch ---------------------------------------------------
extern "C" void kernel_launch(void* const* d_in, const int* in_sizes, int n_in,
                              void* d_out, int out_size)
{
    const float* hs    = (const float*)d_in[0];
    const float* proto = (const float*)d_in[1];
    const float* lens  = (const float*)d_in[2];
    // d_in[3] = mask (bool) — unused; reconstructed from lens
    const float* Q1w = (const float*)d_in[4];
    const float* Q1b = (const float*)d_in[5];
    const float* K1w = (const float*)d_in[6];
    const float* K1b = (const float*)d_in[7];
    const float* V1w = (const float*)d_in[8];
    const float* V1b = (const float*)d_in[9];
    const float* Qw  = (const float*)d_in[10];
    const float* Qb  = (const float*)d_in[11];
    const float* Kw  = (const float*)d_in[12];
    const float* Kb  = (const float*)d_in[13];
    const float* Vw  = (const float*)d_in[14];
    const float* Vb  = (const float*)d_in[15];
    float* out = (float*)d_out;

    float *kvq, *q1, *pf, *pfp, *kv2, *s1, *wf, *wkv, *wr2, *b3, *b2;
    cudaGetSymbolAddress((void**)&kvq, g_kvq);
    cudaGetSymbolAddress((void**)&q1, g_q1);
    cudaGetSymbolAddress((void**)&pf, g_pf);
    cudaGetSymbolAddress((void**)&pfp, g_pfp);
    cudaGetSymbolAddress((void**)&kv2, g_kv2);
    cudaGetSymbolAddress((void**)&s1, g_s1);
    cudaGetSymbolAddress((void**)&wf, g_wf);
    cudaGetSymbolAddress((void**)&wkv, g_wkv);
    cudaGetSymbolAddress((void**)&wr2, g_wr2);
    cudaGetSymbolAddress((void**)&b3, g_b3);
    cudaGetSymbolAddress((void**)&b2, g_b2);
    float* s2 = s1;   // safe reuse: s1 fully consumed before scores2 written

    const int BT = BB * TT;        // 65536
    const int BP = BB * PP;        // 1024
    const long long TH = (long long)TT * HH;
    const long long PH = (long long)PP * HH;
    const long long PT = (long long)PP * TT;
    const long long TP = (long long)TT * PP;
    const long long TF = (long long)TT * NF;
    const long long PKV = (long long)PP * NKV;

    // weight prep
    prep_weights<<<dim3(HH * HH / 256, 6), 256>>>(K1w, V1w, Qw, Q1w, Kw, Vw,
                                                  wf, wr2, wkv);
    fuse_bias<<<5, 256>>>(K1b, V1b, Qb, Kb, Vb, b3, b2);

    // q1 = proto @ Q1_w^T + Q1_b                    [64, 256]
    launch_gemm<64, 128, 32, 32, true, true, true>(dim3(HH / 128, 1, 1),
        proto, 0, HH, wr2, 0, HH, q1, 0, HH, HH, Q1b, 1.f, nullptr, nullptr, 1, 0);

    // fused k1|v1|q2 over all tokens                [65536, 768]
    launch_gemm<128, 128, 64, 32, true, true, true>(dim3(NF / 128, BT / 128, 1),
        hs, 0, HH, wf, 0, HH, kvq, 0, NF, HH, b3, 1.f, nullptr, nullptr, 1, 0);

    // scores1[b,p,t] = q1 . k1 * rsqrt(len_b); masked tiles skipped
    launch_gemm<64, 128, 32, 32, true, false, false>(dim3(TT / 128, 1, BB),
        q1, 0, HH, kvq + 0, TF, NF, s1, PT, TT, HH, nullptr, 1.f, lens, nullptr, 1, 0);

    softmax_rows<<<BP / 8, 256>>>(s1, BP, TT, lens, PP);

    // pf[b] = attn1 @ v1   (split-K x8, per-batch K limit) [64, 256]/batch
    launch_gemm<64, 64, 32, 16, false, false, false>(dim3(HH / 64, 1, BB * NSPLIT),
        s1, PT, TT, kvq + 256, TF, NF, pfp, PH, HH, TT / NSPLIT,
        nullptr, 1.f, nullptr, lens, NSPLIT, (long long)BB * PP * HH);
    reduce_splits<<<(BB * PP * HH + 255) / 256, 256>>>(
        pfp, pf, BB * PP * HH, (long long)BB * PP * HH);

    // fused k2|v2 = pf @ [Kw;Vw]^T + [Kb;Vb]        [1024, 512]
    launch_gemm<64, 128, 32, 32, true, false, true>(dim3(NKV / 128, BP / 64, 1),
        pf, 0, HH, wkv, 0, HH, kv2, 0, NKV, HH, b2, 1.f, nullptr, nullptr, 1, 0);

    // scores2 + fused softmax2 (SMAX epilogue; rows fully in-CTA, N=P=64)
    launch_gemm<128, 64, 32, 32, true, false, false, true>(
        dim3(PP / 64, TT / 128, BB),
        kvq + 512, TF, NF, kv2 + 0, PKV, NKV, s2, TP, PP, HH,
        nullptr, 0.125f, nullptr, nullptr, 1, 0);

    // out[b] = attn2 @ v2                           [4096, 256] per batch
    launch_gemm<128, 128, 64, 32, false, false, false>(dim3(HH / 128, TT / 128, BB),
        s2, TP, PP, kv2 + 256, PKV, NKV, out, TH, HH, PP,
        nullptr, 1.f, nullptr, nullptr, 1, 0);
}

// round 17
// speedup vs baseline: 1.2324x; 1.1154x over previous
#include <cuda_runtime.h>
#include <cuda_bf16.h>
#include <math.h>

// Problem dims (fixed by the dataset)
#define BB 16
#define TT 4096
#define HH 256
#define PP 64

#define NSPLIT 8   // split-K factor for the pf GEMM
#define NF 768     // fused k1|v1|q2 width
#define NKV 512    // fused k2|v2 width

// ---------------- scratch (no allocation allowed) ----------------
__device__ float g_kvq[BB * TT * NF];  // fused [k1 | v1 | q2], 192 MB
__device__ float g_q1[PP * HH];
__device__ float g_pf[BB * PP * HH];
__device__ float g_pfp[NSPLIT * BB * PP * HH];  // split-K partials (8 MB)
__device__ float g_kv2[BB * PP * NKV]; // fused [k2 | v2], 2 MB
__device__ float g_s1[BB * PP * TT];   // 16 MB; reused as s2 (stream-ordered)
__device__ float g_wf[NF * HH];        // fused rounded weights [K1w;V1w;Qw]
__device__ float g_wkv[NKV * HH];      // fused rounded weights [Kw;Vw]
__device__ float g_wr2[HH * HH];       // rounded Q1w
__device__ float g_b3[NF];             // fused biases [K1b;V1b;Qb]
__device__ float g_b2[NKV];            // fused biases [Kb;Vb]

// ---------------- helpers ------------------------------------------------
__device__ __forceinline__ void mma_tf32(float* c, const unsigned* a, const unsigned* b) {
    asm("mma.sync.aligned.m16n8k8.row.col.f32.tf32.tf32.f32 "
        "{%0,%1,%2,%3},{%4,%5,%6,%7},{%8,%9},{%0,%1,%2,%3};"
        : "+f"(c[0]), "+f"(c[1]), "+f"(c[2]), "+f"(c[3])
        : "r"(a[0]), "r"(a[1]), "r"(a[2]), "r"(a[3]), "r"(b[0]), "r"(b[1]));
}

// RNA round to the tf32 grid. MMA truncation of such a value is the identity.
__device__ __forceinline__ unsigned rnd13(unsigned u) { return u + 0x1000u; }
__device__ __forceinline__ float roundtf(float f) {
    unsigned u = __float_as_uint(f);
    u = (u + 0x1000u) & 0xFFFFE000u;
    return __uint_as_float(u);
}

__device__ __forceinline__ void ldsm_x4(unsigned& r0, unsigned& r1,
                                        unsigned& r2, unsigned& r3, unsigned addr) {
    asm volatile("ldmatrix.sync.aligned.m8n8.x4.shared.b16 {%0,%1,%2,%3}, [%4];"
                 : "=r"(r0), "=r"(r1), "=r"(r2), "=r"(r3) : "r"(addr));
}

__device__ __forceinline__ void cpa16s(unsigned dst, const void* src) {
    asm volatile("cp.async.cg.shared.global [%0], [%1], 16;" :: "r"(dst), "l"(src));
}
__device__ __forceinline__ void cp_commit() {
    asm volatile("cp.async.commit_group;");
}
template<int N>
__device__ __forceinline__ void cp_wait() {
    asm volatile("cp.async.wait_group %0;" :: "n"(N));
}

// ---------------- TF32 tensor-core GEMM, 3-stage cp.async + ldmatrix -----
// One barrier per mainloop iteration (see round-14 note).
// MSKIP: kvq-GEMM mode — CTAs in the k1|v1 n-half (n0 < 512) whose whole
//   128-row m-block is >= lens[batch] are skipped. Their outputs stay zero
//   (never written since load) and are provably never read / multiply exact
//   softmax zeros, so results are bit-identical.
#define BK 32
#define NSTG 3

template<int BM, int BN, bool BTRANS>
struct SmemSizes {
    static constexpr int AWORDS = BM * BK;
    static constexpr int BSTNN  = BN + 8;
    static constexpr int BWORDS = BTRANS ? BN * BK : BK * BSTNN;
    static constexpr int STW    = AWORDS + BWORDS;     // words per stage
    static constexpr int BYTES  = NSTG * STW * 4;
};

template<int BM, int BN, int WM, int WN, bool BTRANS, bool RNDA, bool RNDOUT,
         bool SMAX, bool MSKIP>
__global__ __launch_bounds__(256, 2) void gemm_tc(
    const float* __restrict__ A, long long sA, int lda,
    const float* __restrict__ B, long long sB, int ldb,
    float* __restrict__ C, long long sC, int ldc,
    int Kloop,
    const float* __restrict__ bias, float scale,
    const float* __restrict__ lens,
    const float* __restrict__ klim,
    const float* __restrict__ mlens,
    int nsplit, long long sSplit)
{
    constexpr int WCOLS = BN / WN;
    constexpr int MT  = WM / 16;
    constexpr int NTt = WN / 8;
    constexpr int NJ  = NTt / 2;
    constexpr int AWORDS = SmemSizes<BM, BN, BTRANS>::AWORDS;
    constexpr int BSTNN  = SmemSizes<BM, BN, BTRANS>::BSTNN;
    constexpr int STW    = SmemSizes<BM, BN, BTRANS>::STW;

    extern __shared__ unsigned smem_dyn[];
    const unsigned sbase = (unsigned)__cvta_generic_to_shared(smem_dyn);

    const int bz = blockIdx.z;
    const int b  = bz / nsplit;
    const int ks = bz % nsplit;

    const float* Ab = A + (long long)b * sA + (long long)ks * Kloop;
    const float* Bb;
    if (BTRANS) Bb = B + (long long)b * sB + (long long)ks * Kloop;
    else        Bb = B + (long long)b * sB + (long long)ks * Kloop * ldb;
    float* Cb = C + (long long)b * sC + (long long)ks * sSplit;

    const int m0 = blockIdx.y * BM;
    const int n0 = blockIdx.x * BN;

    if (MSKIP && mlens) {
        // m0 is a global token row (single-z launch); batch = m0 / TT.
        const int tok = m0 & (TT - 1);
        if (n0 < 512 && (float)tok >= mlens[m0 / TT]) return;
    }

    float maskLen = 3.0e38f;
    if (lens) {
        float L = lens[b];
        scale = rsqrtf(L);
        maskLen = L;
        if ((float)n0 >= maskLen) return;
    }

    int nIter = Kloop / BK;
    if (klim) {
        int eff = (int)klim[b] - ks * Kloop;
        eff = eff < 0 ? 0 : (eff > Kloop ? Kloop : eff);
        nIter = (eff + BK - 1) / BK;
    }

    const int tid  = threadIdx.x;
    const int lane = tid & 31;
    const int wid  = tid >> 5;
    const int wm   = wid / WCOLS;
    const int wn   = wid % WCOLS;
    const int g    = lane >> 2;
    const int t4   = lane & 3;
    const int l7   = lane & 7;
    const int lr15 = lane & 15;
    const int hb   = lane >> 4;
    const int qb   = (lane >> 3) & 1;

    const int ar = tid >> 3;
    const int aq = tid & 7;

    auto loadA = [&](int s, int k0) {
        const unsigned abase = sbase + (s * STW) * 4;
#pragma unroll
        for (int i = 0; i < BM / 32; i++) {
            const int row = ar + 32 * i;
            cpa16s(abase + (row * BK + ((aq ^ (row & 7)) << 2)) * 4,
                   Ab + (long long)(m0 + row) * lda + k0 + (aq << 2));
        }
    };
    auto loadB = [&](int s, int k0) {
        const unsigned bbase = sbase + (s * STW + AWORDS) * 4;
        if (BTRANS) {
#pragma unroll
            for (int i = 0; i < BN / 32; i++) {
                const int row = ar + 32 * i;
                cpa16s(bbase + (row * BK + ((aq ^ (row & 7)) << 2)) * 4,
                       Bb + (long long)(n0 + row) * ldb + k0 + (aq << 2));
            }
        } else {
            constexpr int QPR = BN / 4;
            constexpr int RPP = 256 / QPR;
            const int bk = tid / QPR;
            const int bq = tid % QPR;
#pragma unroll
            for (int i = 0; i < BK / RPP; i++) {
                const int krow = bk + RPP * i;
                cpa16s(bbase + (krow * BSTNN + bq * 4) * 4,
                       Bb + (long long)(k0 + krow) * ldb + n0 + bq * 4);
            }
        }
    };

    unsigned aRowOff[MT];
#pragma unroll
    for (int i = 0; i < MT; i++)
        aRowOff[i] = (wm * WM + i * 16 + lr15) * BK * 4;
    unsigned bRowOff[NJ];
    if (BTRANS) {
#pragma unroll
        for (int jj = 0; jj < NJ; jj++)
            bRowOff[jj] = (wn * WN + jj * 16 + hb * 8 + l7) * BK * 4;
    }

    float acc[MT][NTt][4];
#pragma unroll
    for (int i = 0; i < MT; i++)
#pragma unroll
        for (int j = 0; j < NTt; j++)
#pragma unroll
            for (int q = 0; q < 4; q++) acc[i][j][q] = 0.f;

    if (nIter > 0) {
        loadA(0, 0);
        loadB(0, 0);
        cp_commit();
        if (nIter > 1) { loadA(1, BK); loadB(1, BK); }
        cp_commit();

        int cb = 0;
        for (int it = 0; it < nIter; it++) {
            cp_wait<1>();
            __syncthreads();

            if (it + 2 < nIter) {
                const int nbuf = (cb == 0) ? 2 : cb - 1;   // (cb+2) mod 3
                loadA(nbuf, (it + 2) * BK);
                loadB(nbuf, (it + 2) * BK);
            }
            cp_commit();          // may be empty (keeps FIFO uniform)

            const unsigned aSt = sbase + (cb * STW) * 4;
            const unsigned bSt = aSt + AWORDS * 4;
            const unsigned* BsNN = smem_dyn + cb * STW + AWORDS;

#pragma unroll
            for (int kss = 0; kss < BK / 8; kss++) {
                const int q0 = kss * 2;
                unsigned af[MT][4];
#pragma unroll
                for (int i = 0; i < MT; i++) {
                    ldsm_x4(af[i][0], af[i][1], af[i][2], af[i][3],
                            aSt + aRowOff[i] + (unsigned)((((q0 + hb) ^ l7)) << 4));
                    if (RNDA) {
                        af[i][0] = rnd13(af[i][0]); af[i][1] = rnd13(af[i][1]);
                        af[i][2] = rnd13(af[i][2]); af[i][3] = rnd13(af[i][3]);
                    }
                }
                unsigned bf[NTt][2];
                if (BTRANS) {
#pragma unroll
                    for (int jj = 0; jj < NJ; jj++) {
                        unsigned w0, w1, w2, w3;
                        ldsm_x4(w0, w1, w2, w3,
                                bSt + bRowOff[jj] + (unsigned)((((q0 + qb) ^ l7)) << 4));
                        bf[2 * jj][0]     = w0;
                        bf[2 * jj][1]     = w1;
                        bf[2 * jj + 1][0] = w2;
                        bf[2 * jj + 1][1] = w3;
                    }
                } else {
                    const int kb = kss * 8;
#pragma unroll
                    for (int j = 0; j < NTt; j++) {
                        const int n = wn * WN + j * 8 + g;
                        bf[j][0] = BsNN[(kb + t4)     * BSTNN + n];
                        bf[j][1] = BsNN[(kb + t4 + 4) * BSTNN + n];
                    }
                }
#pragma unroll
                for (int i = 0; i < MT; i++)
#pragma unroll
                    for (int j = 0; j < NTt; j++)
                        mma_tf32(acc[i][j], af[i], bf[j]);
            }
            cb = (cb == 2) ? 0 : cb + 1;
        }
    }

    // ---- epilogue ----
    if constexpr (SMAX) {
        constexpr int SST = 72;
        float* Ss = (float*)smem_dyn;
        __syncthreads();                      // stage buffers dead; reuse
#pragma unroll
        for (int i = 0; i < MT; i++) {
            const int r0 = wm * WM + i * 16 + g;
#pragma unroll
            for (int j = 0; j < NTt; j++) {
                const int c = wn * WN + j * 8 + 2 * t4;
                Ss[r0 * SST + c]           = acc[i][j][0] * scale;
                Ss[r0 * SST + c + 1]       = acc[i][j][1] * scale;
                Ss[(r0 + 8) * SST + c]     = acc[i][j][2] * scale;
                Ss[(r0 + 8) * SST + c + 1] = acc[i][j][3] * scale;
            }
        }
        __syncthreads();
#pragma unroll
        for (int ii = 0; ii < 16; ii++) {
            const int r = wid * 16 + ii;
            float* p = Ss + r * SST;
            const float v0 = p[lane];
            const float v1 = p[lane + 32];
            float m = fmaxf(fmaxf(-3.0e38f, v0), v1);
#pragma unroll
            for (int o = 16; o; o >>= 1) m = fmaxf(m, __shfl_xor_sync(0xffffffffu, m, o));
            const float e0 = __expf(v0 - m);
            const float e1 = __expf(v1 - m);
            float s = e0 + e1;
#pragma unroll
            for (int o = 16; o; o >>= 1) s += __shfl_xor_sync(0xffffffffu, s, o);
            const float inv = 1.f / s;
            p[lane]      = roundtf(e0 * inv);
            p[lane + 32] = roundtf(e1 * inv);
        }
        __syncthreads();
#pragma unroll
        for (int i = 0; i < (BM * BN) / (256 * 4); i++) {
            const int idx = tid + i * 256;
            const int r = idx >> 4;
            const int q = idx & 15;
            *(float4*)(Cb + (long long)(m0 + r) * ldc + n0 + q * 4) =
                *(const float4*)(Ss + r * SST + q * 4);
        }
    } else {
#pragma unroll
        for (int i = 0; i < MT; i++) {
            const int mrow = m0 + wm * WM + i * 16 + g;
#pragma unroll
            for (int j = 0; j < NTt; j++) {
                const int ncol = n0 + wn * WN + j * 8 + 2 * t4;
                float b0 = bias ? bias[ncol]     : 0.f;
                float b1 = bias ? bias[ncol + 1] : 0.f;
                float v0 = acc[i][j][0] * scale + b0;
                float v1 = acc[i][j][1] * scale + b1;
                float v2 = acc[i][j][2] * scale + b0;
                float v3 = acc[i][j][3] * scale + b1;
                if (lens) {
                    if ((float)ncol     >= maskLen) { v0 = -1e9f; v2 = -1e9f; }
                    if ((float)(ncol+1) >= maskLen) { v1 = -1e9f; v3 = -1e9f; }
                }
                if (RNDOUT) {
                    v0 = roundtf(v0); v1 = roundtf(v1);
                    v2 = roundtf(v2); v3 = roundtf(v3);
                }
                *(float2*)(Cb + (long long)mrow * ldc + ncol)       = make_float2(v0, v1);
                *(float2*)(Cb + (long long)(mrow + 8) * ldc + ncol) = make_float2(v2, v3);
            }
        }
    }
}

// ---------------- weight prep ---------------------------------------------
__global__ void prep_weights(const float* K1w, const float* V1w, const float* Qw,
                             const float* Q1w, const float* Kw, const float* Vw,
                             float* wf, float* wr2, float* wkv)
{
    const int seg = blockIdx.y;
    const float* src;
    switch (seg) {
        case 0: src = K1w; break; case 1: src = V1w; break;
        case 2: src = Qw;  break; case 3: src = Q1w; break;
        case 4: src = Kw;  break; default: src = Vw; break;
    }
    const int i = blockIdx.x * blockDim.x + threadIdx.x;
    const float v = roundtf(src[i]);
    if (seg < 3)      wf[seg * HH * HH + i] = v;
    else if (seg == 3) wr2[i] = v;
    else              wkv[(seg - 4) * HH * HH + i] = v;
}

__global__ void fuse_bias(const float* K1b, const float* V1b, const float* Qb,
                          const float* Kb, const float* Vb,
                          float* b3, float* b2)
{
    const int j = blockIdx.x * blockDim.x + threadIdx.x;
    if (j < 256)        b3[j] = K1b[j];
    else if (j < 512)   b3[j] = V1b[j - 256];
    else if (j < 768)   b3[j] = Qb[j - 512];
    else if (j < 1024)  b2[j - 768] = Kb[j - 768];
    else                b2[j - 768] = Vb[j - 1024];
}

// ---------------- split-K reduce ------------------------------------------
__global__ void reduce_splits(const float* __restrict__ part,
                              float* __restrict__ out,
                              int n, long long stride)
{
    const int i = blockIdx.x * blockDim.x + threadIdx.x;
    if (i >= n) return;
    float s = 0.f;
#pragma unroll
    for (int k = 0; k < NSPLIT; k++) s += part[(long long)k * stride + i];
    out[i] = roundtf(s);
}

// ---------------- softmax over rows (warp per row), in place -------------
__global__ void softmax_rows(float* __restrict__ x, int rows, int cols,
                             const float* __restrict__ lens, int rpb)
{
    const int row = blockIdx.x * (blockDim.x / 32) + (threadIdx.x / 32);
    if (row >= rows) return;
    const int lane = threadIdx.x & 31;
    float* p = x + (long long)row * cols;

    int L = cols;
    if (lens) L = (int)lens[row / rpb];

    float m = -3.0e38f;
    for (int c = lane; c < L; c += 32) m = fmaxf(m, p[c]);
#pragma unroll
    for (int o = 16; o; o >>= 1) m = fmaxf(m, __shfl_xor_sync(0xffffffffu, m, o));

    float s = 0.f;
    for (int c = lane; c < L; c += 32) {
        float e = __expf(p[c] - m);
        p[c] = e;
        s += e;
    }
#pragma unroll
    for (int o = 16; o; o >>= 1) s += __shfl_xor_sync(0xffffffffu, s, o);

    const float inv = 1.f / s;
    for (int c = lane; c < L; c += 32) p[c] = roundtf(p[c] * inv);
    for (int c = L + lane; c < cols; c += 32) p[c] = 0.f;
}

// ---------------- launch helper -------------------------------------------
template<int BM, int BN, int WM, int WN, bool BTRANS, bool RNDA, bool RNDOUT,
         bool SMAX = false, bool MSKIP = false>
static void launch_gemm(dim3 grid,
                        const float* A, long long sA, int lda,
                        const float* B, long long sB, int ldb,
                        float* C, long long sC, int ldc,
                        int Kloop,
                        const float* bias, float scale,
                        const float* lens, const float* klim,
                        const float* mlens,
                        int nsplit, long long sSplit)
{
    constexpr int PIPE = SmemSizes<BM, BN, BTRANS>::BYTES;
    constexpr int SMEM = (SMAX && PIPE < BM * 72 * 4) ? BM * 72 * 4 : PIPE;
    cudaFuncSetAttribute(gemm_tc<BM, BN, WM, WN, BTRANS, RNDA, RNDOUT, SMAX, MSKIP>,
                         cudaFuncAttributeMaxDynamicSharedMemorySize, SMEM);
    gemm_tc<BM, BN, WM, WN, BTRANS, RNDA, RNDOUT, SMAX, MSKIP><<<grid, 256, SMEM>>>(
        A, sA, lda, B, sB, ldb, C, sC, ldc, Kloop, bias, scale, lens, klim,
        mlens, nsplit, sSplit);
}

// ---------------- launch ---------------------------------------------------
extern "C" void kernel_launch(void* const* d_in, const int* in_sizes, int n_in,
                              void* d_out, int out_size)
{
    const float* hs    = (const float*)d_in[0];
    const float* proto = (const float*)d_in[1];
    const float* lens  = (const float*)d_in[2];
    // d_in[3] = mask (bool) — unused; reconstructed from lens
    const float* Q1w = (const float*)d_in[4];
    const float* Q1b = (const float*)d_in[5];
    const float* K1w = (const float*)d_in[6];
    const float* K1b = (const float*)d_in[7];
    const float* V1w = (const float*)d_in[8];
    const float* V1b = (const float*)d_in[9];
    const float* Qw  = (const float*)d_in[10];
    const float* Qb  = (const float*)d_in[11];
    const float* Kw  = (const float*)d_in[12];
    const float* Kb  = (const float*)d_in[13];
    const float* Vw  = (const float*)d_in[14];
    const float* Vb  = (const float*)d_in[15];
    float* out = (float*)d_out;

    float *kvq, *q1, *pf, *pfp, *kv2, *s1, *wf, *wkv, *wr2, *b3, *b2;
    cudaGetSymbolAddress((void**)&kvq, g_kvq);
    cudaGetSymbolAddress((void**)&q1, g_q1);
    cudaGetSymbolAddress((void**)&pf, g_pf);
    cudaGetSymbolAddress((void**)&pfp, g_pfp);
    cudaGetSymbolAddress((void**)&kv2, g_kv2);
    cudaGetSymbolAddress((void**)&s1, g_s1);
    cudaGetSymbolAddress((void**)&wf, g_wf);
    cudaGetSymbolAddress((void**)&wkv, g_wkv);
    cudaGetSymbolAddress((void**)&wr2, g_wr2);
    cudaGetSymbolAddress((void**)&b3, g_b3);
    cudaGetSymbolAddress((void**)&b2, g_b2);
    float* s2 = s1;   // safe reuse: s1 fully consumed before scores2 written

    const int BT = BB * TT;        // 65536
    const int BP = BB * PP;        // 1024
    const long long TH = (long long)TT * HH;
    const long long PH = (long long)PP * HH;
    const long long PT = (long long)PP * TT;
    const long long TP = (long long)TT * PP;
    const long long TF = (long long)TT * NF;
    const long long PKV = (long long)PP * NKV;

    // weight prep
    prep_weights<<<dim3(HH * HH / 256, 6), 256>>>(K1w, V1w, Qw, Q1w, Kw, Vw,
                                                  wf, wr2, wkv);
    fuse_bias<<<5, 256>>>(K1b, V1b, Qb, Kb, Vb, b3, b2);

    // q1 = proto @ Q1_w^T + Q1_b                    [64, 256]
    launch_gemm<64, 128, 32, 32, true, true, true>(dim3(HH / 128, 1, 1),
        proto, 0, HH, wr2, 0, HH, q1, 0, HH, HH, Q1b, 1.f,
        nullptr, nullptr, nullptr, 1, 0);

    // fused k1|v1|q2 over all tokens [65536, 768]; k1/v1 CTAs fully beyond
    // lens[b] are skipped (outputs stay zero, never read / x exact-0)
    launch_gemm<128, 128, 64, 32, true, true, true, false, true>(
        dim3(NF / 128, BT / 128, 1),
        hs, 0, HH, wf, 0, HH, kvq, 0, NF, HH, b3, 1.f,
        nullptr, nullptr, lens, 1, 0);

    // scores1[b,p,t] = q1 . k1 * rsqrt(len_b); masked tiles skipped
    launch_gemm<64, 128, 32, 32, true, false, false>(dim3(TT / 128, 1, BB),
        q1, 0, HH, kvq + 0, TF, NF, s1, PT, TT, HH, nullptr, 1.f,
        lens, nullptr, nullptr, 1, 0);

    softmax_rows<<<BP / 8, 256>>>(s1, BP, TT, lens, PP);

    // pf[b] = attn1 @ v1   (split-K x8, per-batch K limit) [64, 256]/batch
    launch_gemm<64, 64, 32, 16, false, false, false>(dim3(HH / 64, 1, BB * NSPLIT),
        s1, PT, TT, kvq + 256, TF, NF, pfp, PH, HH, TT / NSPLIT,
        nullptr, 1.f, nullptr, lens, nullptr, NSPLIT, (long long)BB * PP * HH);
    reduce_splits<<<(BB * PP * HH + 255) / 256, 256>>>(
        pfp, pf, BB * PP * HH, (long long)BB * PP * HH);

    // fused k2|v2 = pf @ [Kw;Vw]^T + [Kb;Vb]        [1024, 512]
    launch_gemm<64, 128, 32, 32, true, false, true>(dim3(NKV / 128, BP / 64, 1),
        pf, 0, HH, wkv, 0, HH, kv2, 0, NKV, HH, b2, 1.f,
        nullptr, nullptr, nullptr, 1, 0);

    // scores2 + fused softmax2 (SMAX epilogue; rows fully in-CTA, N=P=64)
    launch_gemm<128, 64, 32, 32, true, false, false, true>(
        dim3(PP / 64, TT / 128, BB),
        kvq + 512, TF, NF, kv2 + 0, PKV, NKV, s2, TP, PP, HH,
        nullptr, 0.125f, nullptr, nullptr, nullptr, 1, 0);

    // out[b] = attn2 @ v2                           [4096, 256] per batch
    launch_gemm<128, 128, 64, 32, false, false, false>(dim3(HH / 128, TT / 128, BB),
        s2, TP, PP, kv2 + 256, PKV, NKV, out, TH, HH, PP,
        nullptr, 1.f, nullptr, nullptr, nullptr, 1, 0);
}